// round 16
// baseline (speedup 1.0000x reference)
#include <cuda_runtime.h>
#include <cstdint>

#define SEQ 400
#define BATCH 8
#define DM 256          // d_model
#define SD 512          // source_dim
#define PW 768          // packed projection width: [Q | K | Q2W]
#define ND2 896         // delta columns padded (799 real)
#define BS (BATCH*SEQ)          // 3200
#define BSS (BATCH*SEQ*SEQ)     // 1280000

// Scratch (device globals — no allocations allowed)
__device__ float g_Wcat[SD*PW];      // [w_q | w_k | w_q2@w_k2^T]   (512x768) tf32
__device__ float g_P[BS*PW];         // x @ Wcat                    (3200x768) tf32
__device__ float g_RT[DM*ND2];       // R^T: [d][delta+399]         (256x896) tf32
__device__ float g_S[BS*ND2];        // band of P[:,512:768] @ RT   (3200x896) fp32

// ---------------------------------------------------------------------------
__device__ __forceinline__ float f2tf32(float f) {
    uint32_t u;
    asm("cvt.rna.tf32.f32 %0, %1;" : "=r"(u) : "f"(f));
    return __uint_as_float(u);
}

__device__ __forceinline__ void mma8(float c[4], const uint32_t a[4], const uint32_t b[2]) {
    asm volatile("mma.sync.aligned.m16n8k8.row.col.f32.tf32.tf32.f32 "
        "{%0,%1,%2,%3}, {%4,%5,%6,%7}, {%8,%9}, {%0,%1,%2,%3};"
        : "+f"(c[0]), "+f"(c[1]), "+f"(c[2]), "+f"(c[3])
        : "r"(a[0]), "r"(a[1]), "r"(a[2]), "r"(a[3]), "r"(b[0]), "r"(b[1]));
}

__device__ __forceinline__ void cpa16(uint32_t dst, const float* src, bool p) {
    asm volatile("cp.async.cg.shared.global [%0], [%1], 16, %2;"
                 :: "r"(dst), "l"(src), "r"(p ? 16 : 0));
}
__device__ __forceinline__ void cpa_commit() {
    asm volatile("cp.async.commit_group;");
}
__device__ __forceinline__ void cpa_wait0() {
    asm volatile("cp.async.wait_group 0;");
}

// ---------------------------------------------------------------------------
// Fused setup kernel — all sections independent, one launch, 256 threads:
//   S1: Wcat[:, 0:512) = tf32([w_q | w_k])            blocks [0, 128)
//   S2: RT transposed gather (tf32)                    blocks [128, 240)
//   S3: Wcat[:, 512:768) = tf32(w_q2 @ w_k2^T)         blocks [240, 272)
//   S4: out[BSS..2BSS) = mask outer product            blocks [272, 897)
// (x is not pre-rounded: the P GEMM cvt's A-fragments in-register.)
// ---------------------------------------------------------------------------
#define SB1 128
#define SB2 (SB1 + 112)
#define SB3 (SB2 + 32)
#define SB4 (SB3 + 625)

__global__ __launch_bounds__(256)
void setup_all(const float* __restrict__ wq, const float* __restrict__ wk,
               const float* __restrict__ wq2, const float* __restrict__ wk2,
               const float* __restrict__ rel, const int* __restrict__ mask,
               float* __restrict__ Wcat, float* __restrict__ RT,
               float* __restrict__ out, int out_size)
{
    __shared__ float sh[2176 * 2];
    const int blk = blockIdx.x;
    const int tid = threadIdx.x;

    if (blk < SB1) {
        const int idx = blk * 256 + tid;
        const int row = idx / (DM / 4);
        const int c4  = idx % (DM / 4);
        float4 q = ((const float4*)wq)[idx];
        float4 k = ((const float4*)wk)[idx];
        q.x = f2tf32(q.x); q.y = f2tf32(q.y); q.z = f2tf32(q.z); q.w = f2tf32(q.w);
        k.x = f2tf32(k.x); k.y = f2tf32(k.y); k.z = f2tf32(k.z); k.w = f2tf32(k.w);
        ((float4*)(Wcat + (long)row * PW))[c4] = q;
        ((float4*)(Wcat + (long)row * PW + DM))[c4] = k;
    } else if (blk < SB2) {
        float (*t)[65] = (float(*)[65])sh;
        const int blk2 = blk - SB1;
        const int m0 = (blk2 % 28) * 32;
        const int d0 = (blk2 / 28) * 64;
        const int dl = tid & 63, mb = tid >> 6;
#pragma unroll
        for (int it = 0; it < 8; it++) {
            const int ml = mb * 8 + it;
            const int m = m0 + ml;
            float v = 0.f;
            if (m <= 798) {
                const int delta = m - 399;
                const long off = (delta >= 0) ? (long)delta * DM
                                              : (long)(-delta) * SEQ * DM;
                v = f2tf32(rel[off + d0 + dl]);
            }
            t[ml][dl] = v;
        }
        __syncthreads();
        const int ml2 = tid & 31, db = tid >> 5;
#pragma unroll
        for (int it = 0; it < 8; it++) {
            const int dl2 = db + it * 8;
            RT[(long)(d0 + dl2) * ND2 + m0 + ml2] = t[ml2][dl2];
        }
    } else if (blk < SB3) {
        float (*As)[68] = (float(*)[68])sh;
        float (*Bs)[68] = (float(*)[68])(sh + 16 * 68);
        const int blk2 = blk - SB2;
        const int m0 = (blk2 >> 2) * 64, n0 = (blk2 & 3) * 64;
        const int tx = tid & 15, ty = tid >> 4;
        const int ar = tid >> 2, ak = (tid & 3) * 4;
        float acc[4][4] = {};
        for (int k0 = 0; k0 < DM; k0 += 16) {
            float4 v = *(const float4*)(wq2 + (long)(m0 + ar) * DM + k0 + ak);
            As[ak][ar] = v.x; As[ak+1][ar] = v.y; As[ak+2][ar] = v.z; As[ak+3][ar] = v.w;
            float4 w = *(const float4*)(wk2 + (long)(n0 + ar) * DM + k0 + ak);
            Bs[ak][ar] = w.x; Bs[ak+1][ar] = w.y; Bs[ak+2][ar] = w.z; Bs[ak+3][ar] = w.w;
            __syncthreads();
#pragma unroll
            for (int kk = 0; kk < 16; kk++) {
                const float4 a = *(const float4*)&As[kk][ty * 4];
                const float4 b = *(const float4*)&Bs[kk][tx * 4];
                acc[0][0]+=a.x*b.x; acc[0][1]+=a.x*b.y; acc[0][2]+=a.x*b.z; acc[0][3]+=a.x*b.w;
                acc[1][0]+=a.y*b.x; acc[1][1]+=a.y*b.y; acc[1][2]+=a.y*b.z; acc[1][3]+=a.y*b.w;
                acc[2][0]+=a.z*b.x; acc[2][1]+=a.z*b.y; acc[2][2]+=a.z*b.z; acc[2][3]+=a.z*b.w;
                acc[3][0]+=a.w*b.x; acc[3][1]+=a.w*b.y; acc[3][2]+=a.w*b.z; acc[3][3]+=a.w*b.w;
            }
            __syncthreads();
        }
#pragma unroll
        for (int r = 0; r < 4; r++)
#pragma unroll
            for (int c = 0; c < 4; c++)
                Wcat[(long)(m0 + ty*4 + r) * PW + SD + n0 + tx*4 + c] = f2tf32(acc[r][c]);
    } else if (blk < SB4) {
        // ---- S4: mask outer product, 2 strided float4s per thread
        if (out_size < 2 * BSS) return;
        const int blk2 = blk - SB3;
#pragma unroll
        for (int part = 0; part < 2; part++) {
            const long idx = ((long)blk2 * 512 + part * 256 + tid) * 4;
            if (idx >= BSS) continue;
            const int j = (int)(idx % SEQ);      // SEQ%4==0: no row crossing
            const int bi = (int)(idx / SEQ);
            const int i = bi % SEQ, b = bi / SEQ;
            const float mi = (float)mask[b * SEQ + i];
            float4 o;
            o.x = mi * mask[b * SEQ + j];
            o.y = mi * mask[b * SEQ + j + 1];
            o.z = mi * mask[b * SEQ + j + 2];
            o.w = mi * mask[b * SEQ + j + 3];
            *(float4*)&out[BSS + idx] = o;
        }
    }
}

// ---------------------------------------------------------------------------
// tf32 NN GEMM, 64xNT tile (NT = 128 or 96), BK=32, 256 threads (8 warps
// 2x4, warp tile 32 x NT/4). Two-stage cp.async; conflict-free padded smem
// (A pad 36; B pad 136 for NT=128, 104 for NT=96).
//
// BAND=false (P): C = A[M,K]@B[K,N], grid (N/NT, M/64); M%64==0, N%NT==0.
// BAND=true  (S): per-batch diagonal band, grid (5, 7, BATCH);
//   n0 = max(0,336-m0) + bx*NT; rows >= 400 predicated.
// CVT: apply cvt.rna.tf32 to A-fragments (A raw fp32: used by P on x).
// OTF: tf32-round C on store.
// ---------------------------------------------------------------------------
template <bool OTF, bool BAND, bool CVT, int NT>
__global__ __launch_bounds__(256, 2)
void mmaT(const float* __restrict__ A, const float* __restrict__ B,
          float* __restrict__ C, int K, int lda, int ldb, int ldc)
{
    constexpr int BC  = (NT == 128) ? 136 : 104;
    constexpr int NTC = NT / 32;          // nt count (4 or 3)
    constexpr int ASZ = 64 * 36;
    constexpr int BSZ = 32 * BC;
    extern __shared__ float sh[];
    float* Asb = sh;
    float* Bsb = sh + 2 * ASZ;

    const int tid  = threadIdx.x;
    const int lane = tid & 31;
    const int wid  = tid >> 5;
    const int wm   = wid >> 2;            // 0..1 -> 32-row half
    const int wn   = wid & 3;             // 0..3 -> NT/4-col quarter

    int m0, n0;
    if (BAND) {
        const int b = blockIdx.z;
        A += (long)b * SEQ * lda;
        C += (long)b * SEQ * ldc;
        m0 = blockIdx.y * 64;
        const int nbase = (336 - m0) > 0 ? (336 - m0) : 0;
        n0 = nbase + blockIdx.x * NT;
    } else {
        m0 = blockIdx.y * 64;
        n0 = blockIdx.x * NT;
    }

    const uint32_t uA = (uint32_t)__cvta_generic_to_shared(Asb);
    const uint32_t uB = (uint32_t)__cvta_generic_to_shared(Bsb);

    // A loader: 2 quads; rows (tid>>3)+{0,32}, col (tid&7)*4
    const int arow = tid >> 3;
    const int acol = (tid & 7) * 4;
    const bool aok0 = !BAND || (m0 + arow)      < SEQ;
    const bool aok1 = !BAND || (m0 + arow + 32) < SEQ;
    const float* aptr  = A + (long)(m0 + (aok0 ? arow : 0)) * lda + acol;
    const float* aptr1 = A + (long)(m0 + (aok1 ? arow + 32 : 0)) * lda + acol;
    const uint32_t adst = uA + (uint32_t)(arow * 36 + acol) * 4;

    float acc[2][NTC][4];
#pragma unroll
    for (int mt = 0; mt < 2; mt++)
#pragma unroll
        for (int nt = 0; nt < NTC; nt++)
#pragma unroll
            for (int r = 0; r < 4; r++) acc[mt][nt][r] = 0.f;

    auto load_stage = [&](int buf, int k0) {
        const uint32_t ao = (uint32_t)buf * (ASZ * 4);
        const uint32_t bo = (uint32_t)buf * (BSZ * 4);
        cpa16(adst + ao, aptr + k0, aok0);
        cpa16(adst + ao + (uint32_t)(32 * 36) * 4, aptr1 + k0, aok1);
        if (NT == 128) {
            const int brow = tid >> 5;          // 0..7 (+{0,8,16,24})
            const int bcol = (tid & 31) * 4;
#pragma unroll
            for (int j = 0; j < 4; j++)
                cpa16(uB + bo + (uint32_t)((brow + j * 8) * BC + bcol) * 4,
                      B + (long)(k0 + brow + j * 8) * ldb + n0 + bcol, true);
        } else {
            // NT=96: 32 rows x 24 quads = 768 quads, 3 per thread
#pragma unroll
            for (int j = 0; j < 3; j++) {
                const int q = tid + j * 256;
                const int r = q / 24;
                const int c = (q % 24) * 4;
                cpa16(uB + bo + (uint32_t)(r * BC + c) * 4,
                      B + (long)(k0 + r) * ldb + n0 + c, true);
            }
        }
        cpa_commit();
    };

    load_stage(0, 0);
    cpa_wait0();
    __syncthreads();

    const int nk = K >> 5;
    int buf = 0;
    for (int kt = 0; kt < nk; kt++) {
        const bool more = (kt + 1 < nk);
        if (more) load_stage(buf ^ 1, (kt + 1) << 5);

        const float* Astage = Asb + buf * ASZ;
        const float* Bstage = Bsb + buf * BSZ;
#pragma unroll
        for (int h = 0; h < 4; h++) {
            const int c = h * 8 + (lane & 3);
            uint32_t af[2][4];
            uint32_t bf[NTC][2];
            const float* abase = Astage + (wm * 32 + (lane >> 2)) * 36 + c;
#pragma unroll
            for (int mt = 0; mt < 2; mt++) {
                float a0 = abase[(mt * 16    ) * 36    ];
                float a1 = abase[(mt * 16 + 8) * 36    ];
                float a2 = abase[(mt * 16    ) * 36 + 4];
                float a3 = abase[(mt * 16 + 8) * 36 + 4];
                if (CVT) { a0 = f2tf32(a0); a1 = f2tf32(a1); a2 = f2tf32(a2); a3 = f2tf32(a3); }
                af[mt][0] = __float_as_uint(a0);
                af[mt][1] = __float_as_uint(a1);
                af[mt][2] = __float_as_uint(a2);
                af[mt][3] = __float_as_uint(a3);
            }
#pragma unroll
            for (int nt = 0; nt < NTC; nt++) {
                const int nB = wn * (NT / 4) + nt * 8 + (lane >> 2);
                bf[nt][0] = __float_as_uint(Bstage[(c    ) * BC + nB]);
                bf[nt][1] = __float_as_uint(Bstage[(c + 4) * BC + nB]);
            }
#pragma unroll
            for (int mt = 0; mt < 2; mt++)
#pragma unroll
                for (int nt = 0; nt < NTC; nt++)
                    mma8(acc[mt][nt], af[mt], bf[nt]);
        }

        if (more) {
            cpa_wait0();
            __syncthreads();
            buf ^= 1;
        }
    }

#pragma unroll
    for (int mt = 0; mt < 2; mt++) {
        const int r0 = m0 + wm * 32 + mt * 16 + (lane >> 2);
        const int r1 = r0 + 8;
        const bool ok0 = !BAND || r0 < SEQ;
        const bool ok1 = !BAND || r1 < SEQ;
#pragma unroll
        for (int nt = 0; nt < NTC; nt++) {
            const int cc = n0 + wn * (NT / 4) + nt * 8 + (lane & 3) * 2;
            float v0 = acc[mt][nt][0], v1 = acc[mt][nt][1];
            float v2 = acc[mt][nt][2], v3 = acc[mt][nt][3];
            if (OTF) { v0 = f2tf32(v0); v1 = f2tf32(v1); v2 = f2tf32(v2); v3 = f2tf32(v3); }
            if (ok0) *(float2*)&C[(long)r0 * ldc + cc] = make_float2(v0, v1);
            if (ok1) *(float2*)&C[(long)r1 * ldc + cc] = make_float2(v2, v3);
        }
    }
}

// ---------------------------------------------------------------------------
// E = Q @ K^T fused with combine. 64x96 tile (grid 5x7x8 = 280 CTAs on 296
// 2-residency slots), BK=32, 8 warps 2x4 (warp 32x24, nt=3).
// S diagonal window (64 x 104) prefetched into smem with mainloop stages.
// ---------------------------------------------------------------------------
__global__ __launch_bounds__(256, 2)
void mmaE(const float* __restrict__ P, const float* __restrict__ S,
          float* __restrict__ out)
{
    constexpr int ASZ = 64 * 36;
    constexpr int BSZ = 96 * 36;
    constexpr int SROW = 104;           // 100 data + 4 pad
    extern __shared__ float sh[];
    float* Asb = sh;                    // 2 stages
    float* Bsb = sh + 2 * ASZ;          // 2 stages
    float* Ss  = sh + 2 * ASZ + 2 * BSZ;// 64 x 104

    const int tid  = threadIdx.x;
    const int lane = tid & 31;
    const int wid  = tid >> 5;
    const int wm   = wid >> 2;          // 0..1 -> 32-row half
    const int wn   = wid & 3;           // 0..3 -> 24-col quarter
    const int m0   = blockIdx.y * 64;   // 7 tiles
    const int n0   = blockIdx.x * 96;   // 5 tiles (480 >= 400)
    const int b    = blockIdx.z;
    const int w0   = n0 - m0 + 399;

    const float* A = P + (long)b * SEQ * PW;        // Q
    const float* B = P + (long)b * SEQ * PW + DM;   // K

    const uint32_t uA = (uint32_t)__cvta_generic_to_shared(Asb);
    const uint32_t uB = (uint32_t)__cvta_generic_to_shared(Bsb);
    const uint32_t uS = (uint32_t)__cvta_generic_to_shared(Ss);

    // A loader: 2 quads; rows (tid>>3)+{0,32}, col (tid&7)*4
    const int arow = tid >> 3;
    const int acol = (tid & 7) * 4;
    const bool aok0 = (m0 + arow) < SEQ;
    const bool aok1 = (m0 + arow + 32) < SEQ;
    const float* aptr = A + (long)(m0 + arow) * PW + acol;
    const uint32_t adst = uA + (uint32_t)(arow * 36 + acol) * 4;

    float acc[2][3][4];
#pragma unroll
    for (int mt = 0; mt < 2; mt++)
#pragma unroll
        for (int nt = 0; nt < 3; nt++)
#pragma unroll
            for (int r = 0; r < 4; r++) acc[mt][nt][r] = 0.f;

    // S prefetch: 64 rows x 25 quads = 1600 quads, 8 chunks of 200
    auto s_chunk = [&](int ci) {
        if (tid < 200) {
            const int gq = ci * 200 + tid;       // < 1600
            const int r = gq / 25;
            const int q = gq % 25;
            const int base = (w0 - r) & ~3;
            const int col = base + q * 4;
            const bool ok = ((m0 + r) < SEQ) && (col >= 0) && (col < 893);
            const float* src = S + (long)(b * SEQ + m0 + r) * ND2 + col;
            cpa16(uS + (uint32_t)(r * SROW + q * 4) * 4, src, ok);
        }
    };

    auto load_stage = [&](int buf, int k0, int ci) {
        const uint32_t ao = (uint32_t)buf * (ASZ * 4);
        const uint32_t bo = (uint32_t)buf * (BSZ * 4);
        cpa16(adst + ao, aptr + k0, aok0);
        cpa16(adst + ao + (uint32_t)(32 * 36) * 4, aptr + (long)32 * PW + k0, aok1);
        // B (NT): 96 rows x 32 k = 768 quads, 3 per thread
#pragma unroll
        for (int j = 0; j < 3; j++) {
            const int q = tid + j * 256;
            const int r = q >> 3;                // 0..95
            const int c = (q & 7) * 4;
            const bool ok = (n0 + r) < SEQ;
            cpa16(uB + bo + (uint32_t)(r * 36 + c) * 4,
                  B + (long)(n0 + r) * PW + k0 + c, ok);
        }
        s_chunk(ci);
        cpa_commit();
    };

    const int nk = DM >> 5;   // 8
    load_stage(0, 0, 0);
    cpa_wait0();
    __syncthreads();

    int buf = 0;
    for (int kt = 0; kt < nk; kt++) {
        const bool more = (kt + 1 < nk);
        if (more) load_stage(buf ^ 1, (kt + 1) << 5, kt + 1);

        const float* Astage = Asb + buf * ASZ;
        const float* Bstage = Bsb + buf * BSZ;
#pragma unroll
        for (int h = 0; h < 4; h++) {
            const int c = h * 8 + (lane & 3);
            uint32_t af[2][4];
            uint32_t bf[3][2];
            const float* abase = Astage + (wm * 32 + (lane >> 2)) * 36 + c;
#pragma unroll
            for (int mt = 0; mt < 2; mt++) {
                af[mt][0] = __float_as_uint(abase[(mt * 16    ) * 36    ]);
                af[mt][1] = __float_as_uint(abase[(mt * 16 + 8) * 36    ]);
                af[mt][2] = __float_as_uint(abase[(mt * 16    ) * 36 + 4]);
                af[mt][3] = __float_as_uint(abase[(mt * 16 + 8) * 36 + 4]);
            }
#pragma unroll
            for (int nt = 0; nt < 3; nt++) {
                const int nB = wn * 24 + nt * 8 + (lane >> 2);
                bf[nt][0] = __float_as_uint(Bstage[nB * 36 + c]);
                bf[nt][1] = __float_as_uint(Bstage[nB * 36 + c + 4]);
            }
#pragma unroll
            for (int mt = 0; mt < 2; mt++)
#pragma unroll
                for (int nt = 0; nt < 3; nt++)
                    mma8(acc[mt][nt], af[mt], bf[nt]);
        }

        if (more) {
            cpa_wait0();
            __syncthreads();
            buf ^= 1;
        }
    }

    // ---- fused combine epilogue (S from smem) ----
#pragma unroll
    for (int mt = 0; mt < 2; mt++) {
        const int ibase = m0 + wm * 32 + mt * 16 + (lane >> 2);
#pragma unroll
        for (int half = 0; half < 2; half++) {
            const int i = ibase + half * 8;
            if (i >= SEQ) continue;
            const int r = i - m0;
            const float* srow = Ss + r * SROW + ((w0 - r) & 3) - n0;
            const long obase = (long)b * SEQ * SEQ + (long)i * SEQ;
#pragma unroll
            for (int nt = 0; nt < 3; nt++) {
                const int cc = n0 + wn * 24 + nt * 8 + (lane & 3) * 2;
                if (cc >= SEQ) continue;   // cc even, so cc+1 <= 399
                const float v0 = (acc[mt][nt][half * 2 + 0] + srow[cc])     * 0.0625f;
                const float v1 = (acc[mt][nt][half * 2 + 1] + srow[cc + 1]) * 0.0625f;
                *(float2*)&out[obase + cc] = make_float2(v0, v1);
            }
        }
    }
}

extern "C" void kernel_launch(void* const* d_in, const int* in_sizes, int n_in,
                              void* d_out, int out_size)
{
    const float* x    = (const float*)d_in[0];  // (8,400,512)
    const int*   mask = (const int*)  d_in[1];  // (8,400)
    const float* w_q  = (const float*)d_in[2];  // (512,256)
    const float* w_q2 = (const float*)d_in[3];  // (512,256)
    const float* w_k  = (const float*)d_in[4];  // (512,256)
    const float* w_k2 = (const float*)d_in[5];  // (256,256)
    const float* rel  = (const float*)d_in[6];  // (1,400,400,256)
    float* out = (float*)d_out;

    float *Wcat, *P, *RT, *S;
    cudaGetSymbolAddress((void**)&Wcat, g_Wcat);
    cudaGetSymbolAddress((void**)&P,    g_P);
    cudaGetSymbolAddress((void**)&RT,   g_RT);
    cudaGetSymbolAddress((void**)&S,    g_S);

    const int smem96 = (2 * 64 * 36 + 2 * 32 * 104) * 4;            // 45056
    const int smemE  = (2 * 64 * 36 + 2 * 96 * 36 + 64 * 104) * 4;  // 72704
    cudaFuncSetAttribute(mmaT<true, false, true, 96>,
        cudaFuncAttributeMaxDynamicSharedMemorySize, smem96);
    cudaFuncSetAttribute(mmaT<false, true, false, 96>,
        cudaFuncAttributeMaxDynamicSharedMemorySize, smem96);
    cudaFuncSetAttribute(mmaE,
        cudaFuncAttributeMaxDynamicSharedMemorySize, smemE);

    // 1) Setup (Wcat, RT, mask half of out) — one launch
    setup_all<<<SB4, 256>>>(w_q, w_k, w_q2, w_k2, rel, mask,
                            Wcat, RT, out, out_size);

    // 2) P = x @ Wcat (3200x768x512); 64x96 tiles -> grid (8,50) = 400 CTAs
    //    (vs 64x128 -> 300 CTAs, which quantized badly against 296 slots).
    //    A-fragments cvt'd to tf32 in-register.
    mmaT<true, false, true, 96><<<dim3(PW / 96, BS / 64), 256, smem96>>>(
        x, Wcat, P, SD, SD, PW, PW);

    // 3) S band = P[:,512:768) @ RT, consumed diagonal band only.
    //    Per (b, i0): needed m in [max(0,336-i0), 798-i0] (width <= 463);
    //    5 tiles of 96 from nbase = max(0,336-i0) cover it. 280 CTAs.
    mmaT<false, true, false, 96><<<dim3(5, 7, BATCH), 256, smem96>>>(
        P + SD, RT, S, DM, PW, ND2, ND2);

    // 4) E = Q @ K^T fused with combine + smem S window (280 CTAs)
    mmaE<<<dim3(5, 7, BATCH), 256, smemE>>>(P, S, out);
}

// round 17
// speedup vs baseline: 1.0275x; 1.0275x over previous
#include <cuda_runtime.h>
#include <cstdint>

#define SEQ 400
#define BATCH 8
#define DM 256          // d_model
#define SD 512          // source_dim
#define PW 768          // packed projection width: [Q | K | Q2W]
#define ND2 896         // delta columns padded (799 real)
#define BS (BATCH*SEQ)          // 3200
#define BSS (BATCH*SEQ*SEQ)     // 1280000

// Scratch (device globals — no allocations allowed)
__device__ float g_Wcat[SD*PW];      // [w_q | w_k | w_q2@w_k2^T]   (512x768) tf32
__device__ float g_P[BS*PW];         // x @ Wcat                    (3200x768) tf32
__device__ float g_RT[DM*ND2];       // R^T: [d][delta+399]         (256x896) tf32
__device__ float g_S[BS*ND2];        // band of P[:,512:768] @ RT   (3200x896) fp32

// ---------------------------------------------------------------------------
__device__ __forceinline__ float f2tf32(float f) {
    uint32_t u;
    asm("cvt.rna.tf32.f32 %0, %1;" : "=r"(u) : "f"(f));
    return __uint_as_float(u);
}

__device__ __forceinline__ void mma8(float c[4], const uint32_t a[4], const uint32_t b[2]) {
    asm volatile("mma.sync.aligned.m16n8k8.row.col.f32.tf32.tf32.f32 "
        "{%0,%1,%2,%3}, {%4,%5,%6,%7}, {%8,%9}, {%0,%1,%2,%3};"
        : "+f"(c[0]), "+f"(c[1]), "+f"(c[2]), "+f"(c[3])
        : "r"(a[0]), "r"(a[1]), "r"(a[2]), "r"(a[3]), "r"(b[0]), "r"(b[1]));
}

__device__ __forceinline__ void cpa16(uint32_t dst, const float* src, bool p) {
    asm volatile("cp.async.cg.shared.global [%0], [%1], 16, %2;"
                 :: "r"(dst), "l"(src), "r"(p ? 16 : 0));
}
__device__ __forceinline__ void cpa_commit() {
    asm volatile("cp.async.commit_group;");
}
__device__ __forceinline__ void cpa_wait0() {
    asm volatile("cp.async.wait_group 0;");
}

// ---------------------------------------------------------------------------
// Fused setup kernel — all sections independent, one launch, 256 threads:
//   S1: Wcat[:, 0:512) = tf32([w_q | w_k])            blocks [0, 128)
//   S2: RT transposed gather (tf32)                    blocks [128, 240)
//   S3: Wcat[:, 512:768) = tf32(w_q2 @ w_k2^T)         blocks [240, 272)
// (mask outer product moved to the S GEMM's epilogue; x is cvt'd in P.)
// ---------------------------------------------------------------------------
#define SB1 128
#define SB2 (SB1 + 112)
#define SB3 (SB2 + 32)

__global__ __launch_bounds__(256)
void setup_all(const float* __restrict__ wq, const float* __restrict__ wk,
               const float* __restrict__ wq2, const float* __restrict__ wk2,
               const float* __restrict__ rel,
               float* __restrict__ Wcat, float* __restrict__ RT)
{
    __shared__ float sh[2176 * 2];
    const int blk = blockIdx.x;
    const int tid = threadIdx.x;

    if (blk < SB1) {
        const int idx = blk * 256 + tid;
        const int row = idx / (DM / 4);
        const int c4  = idx % (DM / 4);
        float4 q = ((const float4*)wq)[idx];
        float4 k = ((const float4*)wk)[idx];
        q.x = f2tf32(q.x); q.y = f2tf32(q.y); q.z = f2tf32(q.z); q.w = f2tf32(q.w);
        k.x = f2tf32(k.x); k.y = f2tf32(k.y); k.z = f2tf32(k.z); k.w = f2tf32(k.w);
        ((float4*)(Wcat + (long)row * PW))[c4] = q;
        ((float4*)(Wcat + (long)row * PW + DM))[c4] = k;
    } else if (blk < SB2) {
        float (*t)[65] = (float(*)[65])sh;
        const int blk2 = blk - SB1;
        const int m0 = (blk2 % 28) * 32;
        const int d0 = (blk2 / 28) * 64;
        const int dl = tid & 63, mb = tid >> 6;
#pragma unroll
        for (int it = 0; it < 8; it++) {
            const int ml = mb * 8 + it;
            const int m = m0 + ml;
            float v = 0.f;
            if (m <= 798) {
                const int delta = m - 399;
                const long off = (delta >= 0) ? (long)delta * DM
                                              : (long)(-delta) * SEQ * DM;
                v = f2tf32(rel[off + d0 + dl]);
            }
            t[ml][dl] = v;
        }
        __syncthreads();
        const int ml2 = tid & 31, db = tid >> 5;
#pragma unroll
        for (int it = 0; it < 8; it++) {
            const int dl2 = db + it * 8;
            RT[(long)(d0 + dl2) * ND2 + m0 + ml2] = t[ml2][dl2];
        }
    } else if (blk < SB3) {
        float (*As)[68] = (float(*)[68])sh;
        float (*Bs)[68] = (float(*)[68])(sh + 16 * 68);
        const int blk2 = blk - SB2;
        const int m0 = (blk2 >> 2) * 64, n0 = (blk2 & 3) * 64;
        const int tx = tid & 15, ty = tid >> 4;
        const int ar = tid >> 2, ak = (tid & 3) * 4;
        float acc[4][4] = {};
        for (int k0 = 0; k0 < DM; k0 += 16) {
            float4 v = *(const float4*)(wq2 + (long)(m0 + ar) * DM + k0 + ak);
            As[ak][ar] = v.x; As[ak+1][ar] = v.y; As[ak+2][ar] = v.z; As[ak+3][ar] = v.w;
            float4 w = *(const float4*)(wk2 + (long)(n0 + ar) * DM + k0 + ak);
            Bs[ak][ar] = w.x; Bs[ak+1][ar] = w.y; Bs[ak+2][ar] = w.z; Bs[ak+3][ar] = w.w;
            __syncthreads();
#pragma unroll
            for (int kk = 0; kk < 16; kk++) {
                const float4 a = *(const float4*)&As[kk][ty * 4];
                const float4 b = *(const float4*)&Bs[kk][tx * 4];
                acc[0][0]+=a.x*b.x; acc[0][1]+=a.x*b.y; acc[0][2]+=a.x*b.z; acc[0][3]+=a.x*b.w;
                acc[1][0]+=a.y*b.x; acc[1][1]+=a.y*b.y; acc[1][2]+=a.y*b.z; acc[1][3]+=a.y*b.w;
                acc[2][0]+=a.z*b.x; acc[2][1]+=a.z*b.y; acc[2][2]+=a.z*b.z; acc[2][3]+=a.z*b.w;
                acc[3][0]+=a.w*b.x; acc[3][1]+=a.w*b.y; acc[3][2]+=a.w*b.z; acc[3][3]+=a.w*b.w;
            }
            __syncthreads();
        }
#pragma unroll
        for (int r = 0; r < 4; r++)
#pragma unroll
            for (int c = 0; c < 4; c++)
                Wcat[(long)(m0 + ty*4 + r) * PW + SD + n0 + tx*4 + c] = f2tf32(acc[r][c]);
    }
}

// ---------------------------------------------------------------------------
// tf32 NN GEMM, 64xNT tile (NT = 128 or 96), BK=32, 256 threads (8 warps
// 2x4, warp tile 32 x NT/4). Two-stage cp.async; conflict-free padded smem
// (A pad 36; B pad 136 for NT=128, 104 for NT=96).
//
// BAND=false (P): C = A[M,K]@B[K,N], grid (N/NT, M/64); M%64==0, N%NT==0.
// BAND=true  (S): per-batch diagonal band, grid (5, 7, BATCH);
//   n0 = max(0,336-m0) + bx*NT; rows >= 400 predicated.
// MASKW (with BAND): epilogue also writes the mask outer product into
//   out[BSS + b*SEQ*SEQ + i*SEQ + j] at j = m + i - 399 — the per-row
//   bijection means the band tiles cover every (b,i,j) exactly once.
// CVT: apply cvt.rna.tf32 to A-fragments (A raw fp32: used by P on x).
// OTF: tf32-round C on store.
// ---------------------------------------------------------------------------
template <bool OTF, bool BAND, bool CVT, int NT, bool MASKW>
__global__ __launch_bounds__(256, 2)
void mmaT(const float* __restrict__ A, const float* __restrict__ B,
          float* __restrict__ C, int K, int lda, int ldb, int ldc,
          const int* __restrict__ mask, float* __restrict__ out, int out_size)
{
    constexpr int BC  = (NT == 128) ? 136 : 104;
    constexpr int NTC = NT / 32;          // nt count (4 or 3)
    constexpr int ASZ = 64 * 36;
    constexpr int BSZ = 32 * BC;
    extern __shared__ float sh[];
    float* Asb = sh;
    float* Bsb = sh + 2 * ASZ;

    const int tid  = threadIdx.x;
    const int lane = tid & 31;
    const int wid  = tid >> 5;
    const int wm   = wid >> 2;            // 0..1 -> 32-row half
    const int wn   = wid & 3;             // 0..3 -> NT/4-col quarter

    int m0, n0;
    if (BAND) {
        const int b = blockIdx.z;
        A += (long)b * SEQ * lda;
        C += (long)b * SEQ * ldc;
        m0 = blockIdx.y * 64;
        const int nbase = (336 - m0) > 0 ? (336 - m0) : 0;
        n0 = nbase + blockIdx.x * NT;
    } else {
        m0 = blockIdx.y * 64;
        n0 = blockIdx.x * NT;
    }

    const uint32_t uA = (uint32_t)__cvta_generic_to_shared(Asb);
    const uint32_t uB = (uint32_t)__cvta_generic_to_shared(Bsb);

    // A loader: 2 quads; rows (tid>>3)+{0,32}, col (tid&7)*4
    const int arow = tid >> 3;
    const int acol = (tid & 7) * 4;
    const bool aok0 = !BAND || (m0 + arow)      < SEQ;
    const bool aok1 = !BAND || (m0 + arow + 32) < SEQ;
    const float* aptr  = A + (long)(m0 + (aok0 ? arow : 0)) * lda + acol;
    const float* aptr1 = A + (long)(m0 + (aok1 ? arow + 32 : 0)) * lda + acol;
    const uint32_t adst = uA + (uint32_t)(arow * 36 + acol) * 4;

    float acc[2][NTC][4];
#pragma unroll
    for (int mt = 0; mt < 2; mt++)
#pragma unroll
        for (int nt = 0; nt < NTC; nt++)
#pragma unroll
            for (int r = 0; r < 4; r++) acc[mt][nt][r] = 0.f;

    auto load_stage = [&](int buf, int k0) {
        const uint32_t ao = (uint32_t)buf * (ASZ * 4);
        const uint32_t bo = (uint32_t)buf * (BSZ * 4);
        cpa16(adst + ao, aptr + k0, aok0);
        cpa16(adst + ao + (uint32_t)(32 * 36) * 4, aptr1 + k0, aok1);
        if (NT == 128) {
            const int brow = tid >> 5;          // 0..7 (+{0,8,16,24})
            const int bcol = (tid & 31) * 4;
#pragma unroll
            for (int j = 0; j < 4; j++)
                cpa16(uB + bo + (uint32_t)((brow + j * 8) * BC + bcol) * 4,
                      B + (long)(k0 + brow + j * 8) * ldb + n0 + bcol, true);
        } else {
            // NT=96: 32 rows x 24 quads = 768 quads, 3 per thread
#pragma unroll
            for (int j = 0; j < 3; j++) {
                const int q = tid + j * 256;
                const int r = q / 24;
                const int c = (q % 24) * 4;
                cpa16(uB + bo + (uint32_t)(r * BC + c) * 4,
                      B + (long)(k0 + r) * ldb + n0 + c, true);
            }
        }
        cpa_commit();
    };

    load_stage(0, 0);
    cpa_wait0();
    __syncthreads();

    const int nk = K >> 5;
    int buf = 0;
    for (int kt = 0; kt < nk; kt++) {
        const bool more = (kt + 1 < nk);
        if (more) load_stage(buf ^ 1, (kt + 1) << 5);

        const float* Astage = Asb + buf * ASZ;
        const float* Bstage = Bsb + buf * BSZ;
#pragma unroll
        for (int h = 0; h < 4; h++) {
            const int c = h * 8 + (lane & 3);
            uint32_t af[2][4];
            uint32_t bf[NTC][2];
            const float* abase = Astage + (wm * 32 + (lane >> 2)) * 36 + c;
#pragma unroll
            for (int mt = 0; mt < 2; mt++) {
                float a0 = abase[(mt * 16    ) * 36    ];
                float a1 = abase[(mt * 16 + 8) * 36    ];
                float a2 = abase[(mt * 16    ) * 36 + 4];
                float a3 = abase[(mt * 16 + 8) * 36 + 4];
                if (CVT) { a0 = f2tf32(a0); a1 = f2tf32(a1); a2 = f2tf32(a2); a3 = f2tf32(a3); }
                af[mt][0] = __float_as_uint(a0);
                af[mt][1] = __float_as_uint(a1);
                af[mt][2] = __float_as_uint(a2);
                af[mt][3] = __float_as_uint(a3);
            }
#pragma unroll
            for (int nt = 0; nt < NTC; nt++) {
                const int nB = wn * (NT / 4) + nt * 8 + (lane >> 2);
                bf[nt][0] = __float_as_uint(Bstage[(c    ) * BC + nB]);
                bf[nt][1] = __float_as_uint(Bstage[(c + 4) * BC + nB]);
            }
#pragma unroll
            for (int mt = 0; mt < 2; mt++)
#pragma unroll
                for (int nt = 0; nt < NTC; nt++)
                    mma8(acc[mt][nt], af[mt], bf[nt]);
        }

        if (more) {
            cpa_wait0();
            __syncthreads();
            buf ^= 1;
        }
    }

    const bool wmask = MASKW && (out_size >= 2 * BSS);
    const int bz = BAND ? blockIdx.z : 0;
#pragma unroll
    for (int mt = 0; mt < 2; mt++) {
        const int r0 = m0 + wm * 32 + mt * 16 + (lane >> 2);
        const int r1 = r0 + 8;
        const bool ok0 = !BAND || r0 < SEQ;
        const bool ok1 = !BAND || r1 < SEQ;
        float mi0 = 0.f, mi1 = 0.f;
        if (MASKW) {
            if (wmask && ok0) mi0 = (float)mask[bz * SEQ + r0];
            if (wmask && ok1) mi1 = (float)mask[bz * SEQ + r1];
        }
#pragma unroll
        for (int nt = 0; nt < NTC; nt++) {
            const int cc = n0 + wn * (NT / 4) + nt * 8 + (lane & 3) * 2;
            float v0 = acc[mt][nt][0], v1 = acc[mt][nt][1];
            float v2 = acc[mt][nt][2], v3 = acc[mt][nt][3];
            if (OTF) { v0 = f2tf32(v0); v1 = f2tf32(v1); v2 = f2tf32(v2); v3 = f2tf32(v3); }
            if (ok0) *(float2*)&C[(long)r0 * ldc + cc] = make_float2(v0, v1);
            if (ok1) *(float2*)&C[(long)r1 * ldc + cc] = make_float2(v2, v3);
            if (MASKW && wmask) {
                // j = m + i - 399 (bijection per row); write mask product
                const int j0a = cc + r0 - 399;
                const int j0b = cc + r1 - 399;
                const long ob0 = (long)BSS + ((long)bz * SEQ + r0) * SEQ;
                const long ob1 = (long)BSS + ((long)bz * SEQ + r1) * SEQ;
                if (ok0) {
                    if ((unsigned)j0a < SEQ)
                        out[ob0 + j0a] = mi0 * (float)mask[bz * SEQ + j0a];
                    if ((unsigned)(j0a + 1) < SEQ)
                        out[ob0 + j0a + 1] = mi0 * (float)mask[bz * SEQ + j0a + 1];
                }
                if (ok1) {
                    if ((unsigned)j0b < SEQ)
                        out[ob1 + j0b] = mi1 * (float)mask[bz * SEQ + j0b];
                    if ((unsigned)(j0b + 1) < SEQ)
                        out[ob1 + j0b + 1] = mi1 * (float)mask[bz * SEQ + j0b + 1];
                }
            }
        }
    }
}

// ---------------------------------------------------------------------------
// E = Q @ K^T fused with combine. 64x96 tile (grid 5x7x8 = 280 CTAs on 296
// 2-residency slots), BK=32, 8 warps 2x4 (warp 32x24, nt=3).
// S diagonal window (64 x 104) prefetched into smem with mainloop stages.
// ---------------------------------------------------------------------------
__global__ __launch_bounds__(256, 2)
void mmaE(const float* __restrict__ P, const float* __restrict__ S,
          float* __restrict__ out)
{
    constexpr int ASZ = 64 * 36;
    constexpr int BSZ = 96 * 36;
    constexpr int SROW = 104;           // 100 data + 4 pad
    extern __shared__ float sh[];
    float* Asb = sh;                    // 2 stages
    float* Bsb = sh + 2 * ASZ;          // 2 stages
    float* Ss  = sh + 2 * ASZ + 2 * BSZ;// 64 x 104

    const int tid  = threadIdx.x;
    const int lane = tid & 31;
    const int wid  = tid >> 5;
    const int wm   = wid >> 2;          // 0..1 -> 32-row half
    const int wn   = wid & 3;           // 0..3 -> 24-col quarter
    const int m0   = blockIdx.y * 64;   // 7 tiles
    const int n0   = blockIdx.x * 96;   // 5 tiles (480 >= 400)
    const int b    = blockIdx.z;
    const int w0   = n0 - m0 + 399;

    const float* A = P + (long)b * SEQ * PW;        // Q
    const float* B = P + (long)b * SEQ * PW + DM;   // K

    const uint32_t uA = (uint32_t)__cvta_generic_to_shared(Asb);
    const uint32_t uB = (uint32_t)__cvta_generic_to_shared(Bsb);
    const uint32_t uS = (uint32_t)__cvta_generic_to_shared(Ss);

    // A loader: 2 quads; rows (tid>>3)+{0,32}, col (tid&7)*4
    const int arow = tid >> 3;
    const int acol = (tid & 7) * 4;
    const bool aok0 = (m0 + arow) < SEQ;
    const bool aok1 = (m0 + arow + 32) < SEQ;
    const float* aptr = A + (long)(m0 + arow) * PW + acol;
    const uint32_t adst = uA + (uint32_t)(arow * 36 + acol) * 4;

    float acc[2][3][4];
#pragma unroll
    for (int mt = 0; mt < 2; mt++)
#pragma unroll
        for (int nt = 0; nt < 3; nt++)
#pragma unroll
            for (int r = 0; r < 4; r++) acc[mt][nt][r] = 0.f;

    // S prefetch: 64 rows x 25 quads = 1600 quads, 8 chunks of 200
    auto s_chunk = [&](int ci) {
        if (tid < 200) {
            const int gq = ci * 200 + tid;       // < 1600
            const int r = gq / 25;
            const int q = gq % 25;
            const int base = (w0 - r) & ~3;
            const int col = base + q * 4;
            const bool ok = ((m0 + r) < SEQ) && (col >= 0) && (col < 893);
            const float* src = S + (long)(b * SEQ + m0 + r) * ND2 + col;
            cpa16(uS + (uint32_t)(r * SROW + q * 4) * 4, src, ok);
        }
    };

    auto load_stage = [&](int buf, int k0, int ci) {
        const uint32_t ao = (uint32_t)buf * (ASZ * 4);
        const uint32_t bo = (uint32_t)buf * (BSZ * 4);
        cpa16(adst + ao, aptr + k0, aok0);
        cpa16(adst + ao + (uint32_t)(32 * 36) * 4, aptr + (long)32 * PW + k0, aok1);
        // B (NT): 96 rows x 32 k = 768 quads, 3 per thread
#pragma unroll
        for (int j = 0; j < 3; j++) {
            const int q = tid + j * 256;
            const int r = q >> 3;                // 0..95
            const int c = (q & 7) * 4;
            const bool ok = (n0 + r) < SEQ;
            cpa16(uB + bo + (uint32_t)(r * 36 + c) * 4,
                  B + (long)(n0 + r) * PW + k0 + c, ok);
        }
        s_chunk(ci);
        cpa_commit();
    };

    const int nk = DM >> 5;   // 8
    load_stage(0, 0, 0);
    cpa_wait0();
    __syncthreads();

    int buf = 0;
    for (int kt = 0; kt < nk; kt++) {
        const bool more = (kt + 1 < nk);
        if (more) load_stage(buf ^ 1, (kt + 1) << 5, kt + 1);

        const float* Astage = Asb + buf * ASZ;
        const float* Bstage = Bsb + buf * BSZ;
#pragma unroll
        for (int h = 0; h < 4; h++) {
            const int c = h * 8 + (lane & 3);
            uint32_t af[2][4];
            uint32_t bf[3][2];
            const float* abase = Astage + (wm * 32 + (lane >> 2)) * 36 + c;
#pragma unroll
            for (int mt = 0; mt < 2; mt++) {
                af[mt][0] = __float_as_uint(abase[(mt * 16    ) * 36    ]);
                af[mt][1] = __float_as_uint(abase[(mt * 16 + 8) * 36    ]);
                af[mt][2] = __float_as_uint(abase[(mt * 16    ) * 36 + 4]);
                af[mt][3] = __float_as_uint(abase[(mt * 16 + 8) * 36 + 4]);
            }
#pragma unroll
            for (int nt = 0; nt < 3; nt++) {
                const int nB = wn * 24 + nt * 8 + (lane >> 2);
                bf[nt][0] = __float_as_uint(Bstage[nB * 36 + c]);
                bf[nt][1] = __float_as_uint(Bstage[nB * 36 + c + 4]);
            }
#pragma unroll
            for (int mt = 0; mt < 2; mt++)
#pragma unroll
                for (int nt = 0; nt < 3; nt++)
                    mma8(acc[mt][nt], af[mt], bf[nt]);
        }

        if (more) {
            cpa_wait0();
            __syncthreads();
            buf ^= 1;
        }
    }

    // ---- fused combine epilogue (S from smem) ----
#pragma unroll
    for (int mt = 0; mt < 2; mt++) {
        const int ibase = m0 + wm * 32 + mt * 16 + (lane >> 2);
#pragma unroll
        for (int half = 0; half < 2; half++) {
            const int i = ibase + half * 8;
            if (i >= SEQ) continue;
            const int r = i - m0;
            const float* srow = Ss + r * SROW + ((w0 - r) & 3) - n0;
            const long obase = (long)b * SEQ * SEQ + (long)i * SEQ;
#pragma unroll
            for (int nt = 0; nt < 3; nt++) {
                const int cc = n0 + wn * 24 + nt * 8 + (lane & 3) * 2;
                if (cc >= SEQ) continue;   // cc even, so cc+1 <= 399
                const float v0 = (acc[mt][nt][half * 2 + 0] + srow[cc])     * 0.0625f;
                const float v1 = (acc[mt][nt][half * 2 + 1] + srow[cc + 1]) * 0.0625f;
                *(float2*)&out[obase + cc] = make_float2(v0, v1);
            }
        }
    }
}

extern "C" void kernel_launch(void* const* d_in, const int* in_sizes, int n_in,
                              void* d_out, int out_size)
{
    const float* x    = (const float*)d_in[0];  // (8,400,512)
    const int*   mask = (const int*)  d_in[1];  // (8,400)
    const float* w_q  = (const float*)d_in[2];  // (512,256)
    const float* w_q2 = (const float*)d_in[3];  // (512,256)
    const float* w_k  = (const float*)d_in[4];  // (512,256)
    const float* w_k2 = (const float*)d_in[5];  // (256,256)
    const float* rel  = (const float*)d_in[6];  // (1,400,400,256)
    float* out = (float*)d_out;

    float *Wcat, *P, *RT, *S;
    cudaGetSymbolAddress((void**)&Wcat, g_Wcat);
    cudaGetSymbolAddress((void**)&P,    g_P);
    cudaGetSymbolAddress((void**)&RT,   g_RT);
    cudaGetSymbolAddress((void**)&S,    g_S);

    const int smemP = (2 * 64 * 36 + 2 * 32 * 136) * 4;             // 53248
    const int smemS = (2 * 64 * 36 + 2 * 32 * 104) * 4;             // 45056
    const int smemE = (2 * 64 * 36 + 2 * 96 * 36 + 64 * 104) * 4;   // 72704
    cudaFuncSetAttribute(mmaT<true, false, true, 128, false>,
        cudaFuncAttributeMaxDynamicSharedMemorySize, smemP);
    cudaFuncSetAttribute(mmaT<false, true, false, 96, true>,
        cudaFuncAttributeMaxDynamicSharedMemorySize, smemS);
    cudaFuncSetAttribute(mmaE,
        cudaFuncAttributeMaxDynamicSharedMemorySize, smemE);

    // 1) Setup (Wcat, RT) — one small launch (272 blocks)
    setup_all<<<SB3, 256>>>(w_q, w_k, w_q2, w_k2, rel, Wcat, RT);

    // 2) P = x @ Wcat (3200x768x512); 64x128 tiles, 300 CTAs (R15 config —
    //    NT=96 regressed). A-fragments cvt'd to tf32 in-register.
    mmaT<true, false, true, 128, false><<<dim3(PW / 128, BS / 64), 256, smemP>>>(
        x, Wcat, P, SD, SD, PW, PW, nullptr, nullptr, 0);

    // 3) S band = P[:,512:768) @ RT (consumed diagonal band only, 280 CTAs).
    //    Epilogue ALSO writes the mask outer product into out[BSS..2BSS):
    //    j = m + i - 399 is a bijection per row and the band covers every
    //    valid (i,j) exactly once — replaces setup's 5.1 MB S4 section.
    mmaT<false, true, false, 96, true><<<dim3(5, 7, BATCH), 256, smemS>>>(
        P + SD, RT, S, DM, PW, ND2, ND2, mask, out, out_size);

    // 4) E = Q @ K^T fused with combine + smem S window (280 CTAs)
    mmaE<<<dim3(5, 7, BATCH), 256, smemE>>>(P, S, out);
}